// round 1
// baseline (speedup 1.0000x reference)
#include <cuda_runtime.h>
#include <cuda_bf16.h>
#include <cfloat>
#include <cstdint>

#define NUM_HEADS 4
#define OUT_DIM   256
#define HID       512
#define BATCH     64
#define NQ        256          // NUM_HEADS * BATCH
#define TOPK      16
#define N_MEM_MAX 500000

// ---------------- scratch (static device memory; no allocs allowed) ----------
__device__ float g_q[NQ * OUT_DIM];                       // layernormed queries [q][d]
__device__ float g_scores[(size_t)N_MEM_MAX * NQ];        // scores [q][row]  (transposed!)

// ---------------- K1: q = LN(hidden @ Wp + bp) per (head, batch) row ---------
__global__ void qproj_kernel(const float* __restrict__ hidden,
                             const float* __restrict__ Wp,
                             const float* __restrict__ bp) {
    __shared__ float hs[HID];
    __shared__ float red[OUT_DIM];
    const int qidx = blockIdx.x;        // h*64 + b
    const int h = qidx >> 6;
    const int b = qidx & 63;
    const int d = threadIdx.x;

    for (int k = d; k < HID; k += OUT_DIM) hs[k] = hidden[b * HID + k];
    __syncthreads();

    const int j = h * OUT_DIM + d;
    float acc = bp[j];
#pragma unroll 8
    for (int k = 0; k < HID; k++) acc += hs[k] * Wp[k * (NUM_HEADS * OUT_DIM) + j];

    // mean
    red[d] = acc; __syncthreads();
    for (int s = 128; s > 0; s >>= 1) { if (d < s) red[d] += red[d + s]; __syncthreads(); }
    const float mean = red[0] * (1.0f / OUT_DIM);
    __syncthreads();
    // var (population, ddof=0, two-pass like jnp.var)
    const float dx = acc - mean;
    red[d] = dx * dx; __syncthreads();
    for (int s = 128; s > 0; s >>= 1) { if (d < s) red[d] += red[d + s]; __syncthreads(); }
    const float var = red[0] * (1.0f / OUT_DIM);

    g_q[qidx * OUT_DIM + d] = dx * rsqrtf(var + 1e-5f);
}

// ---------------- K2: scores[q][row] = mem[row,:] . q[q,:]  (fp32, f32x2 FMA) -
#define TM        128
#define KT        8
#define NKT       (OUT_DIM / KT)   // 32
#define AS_STRIDE 132              // padded (4*132 mod 128B keeps STS conflict-free)
#define BS_STRIDE 260

__device__ __forceinline__ unsigned long long pack2(float lo, float hi) {
    unsigned long long r;
    asm("mov.b64 %0, {%1, %2};" : "=l"(r) : "f"(lo), "f"(hi));
    return r;
}
__device__ __forceinline__ unsigned long long fma2(unsigned long long a,
                                                   unsigned long long b,
                                                   unsigned long long c) {
    unsigned long long d;
    asm("fma.rn.f32x2 %0, %1, %2, %3;" : "=l"(d) : "l"(a), "l"(b), "l"(c));
    return d;
}
__device__ __forceinline__ float u64_lo(unsigned long long v) {
    return __uint_as_float((unsigned)(v & 0xffffffffu));
}
__device__ __forceinline__ float u64_hi(unsigned long long v) {
    return __uint_as_float((unsigned)(v >> 32));
}

__global__ __launch_bounds__(512, 1) void score_kernel(const float* __restrict__ mem,
                                                       int n_mem) {
    __shared__ __align__(16) float As[2][KT][AS_STRIDE];  // As[k][row]
    __shared__ __align__(16) float Bs[2][KT][BS_STRIDE];  // Bs[k][q]

    const int tid  = threadIdx.x;
    const int lane = tid & 31;
    const int rgrp = lane & 15;      // rows rgrp*8 .. rgrp*8+7 (contiguous -> coalesced STG)
    const int qgrp = tid >> 4;       // 0..31 -> queries qgrp*8 .. +7
    const int row0 = blockIdx.x * TM;

    const int ar = tid >> 1;         // 0..127 (A loader rows, tid<256)
    const int kb = (tid & 1) * 4;    // k sub-offset for both loaders
    const int bq = tid >> 1;         // 0..255 (B loader query row)

    float4 aReg = make_float4(0.f, 0.f, 0.f, 0.f);
    float4 bReg = make_float4(0.f, 0.f, 0.f, 0.f);

    unsigned long long acc[8][4];
#pragma unroll
    for (int i = 0; i < 8; i++)
#pragma unroll
        for (int j = 0; j < 4; j++) acc[i][j] = 0ull;

#define LDG_TILE(ktile)                                                              \
    do {                                                                             \
        if (tid < 256) {                                                             \
            int r_ = row0 + ar;                                                      \
            aReg = (r_ < n_mem)                                                      \
                ? *(const float4*)(mem + (size_t)r_ * OUT_DIM + (ktile) * KT + kb)   \
                : make_float4(0.f, 0.f, 0.f, 0.f);                                   \
        }                                                                            \
        bReg = *(const float4*)(g_q + bq * OUT_DIM + (ktile) * KT + kb);             \
    } while (0)

#define STS_TILE(buf)                                                                \
    do {                                                                             \
        if (tid < 256) {                                                             \
            As[buf][kb + 0][ar] = aReg.x; As[buf][kb + 1][ar] = aReg.y;              \
            As[buf][kb + 2][ar] = aReg.z; As[buf][kb + 3][ar] = aReg.w;              \
        }                                                                            \
        Bs[buf][kb + 0][bq] = bReg.x; Bs[buf][kb + 1][bq] = bReg.y;                  \
        Bs[buf][kb + 2][bq] = bReg.z; Bs[buf][kb + 3][bq] = bReg.w;                  \
    } while (0)

    LDG_TILE(0);
    STS_TILE(0);
    __syncthreads();

    int cur = 0;
    for (int kt = 0; kt < NKT; kt++) {
        if (kt + 1 < NKT) LDG_TILE(kt + 1);
#pragma unroll
        for (int k = 0; k < KT; k++) {
            const unsigned long long* ap =
                reinterpret_cast<const unsigned long long*>(&As[cur][k][rgrp * 8]);
            const unsigned long long ra0 = ap[0], ra1 = ap[1], ra2 = ap[2], ra3 = ap[3];
            const float* bpp = &Bs[cur][k][qgrp * 8];
#pragma unroll
            for (int i = 0; i < 8; i++) {
                const unsigned long long qq = pack2(bpp[i], bpp[i]);
                acc[i][0] = fma2(qq, ra0, acc[i][0]);
                acc[i][1] = fma2(qq, ra1, acc[i][1]);
                acc[i][2] = fma2(qq, ra2, acc[i][2]);
                acc[i][3] = fma2(qq, ra3, acc[i][3]);
            }
        }
        if (kt + 1 < NKT) {
            STS_TILE(cur ^ 1);
            __syncthreads();
            cur ^= 1;
        }
    }

    // epilogue: scores stored transposed [q][row]; rows contiguous per thread
    const int rbase = row0 + rgrp * 8;
#pragma unroll
    for (int i = 0; i < 8; i++) {
        const int q = qgrp * 8 + i;
        float* dst = g_scores + (size_t)q * n_mem;
        float o[8];
#pragma unroll
        for (int j = 0; j < 4; j++) { o[2 * j] = u64_lo(acc[i][j]); o[2 * j + 1] = u64_hi(acc[i][j]); }
        if (rbase + 7 < n_mem) {
            *(float4*)(dst + rbase)     = make_float4(o[0], o[1], o[2], o[3]);
            *(float4*)(dst + rbase + 4) = make_float4(o[4], o[5], o[6], o[7]);
        } else {
            for (int t = 0; t < 8; t++)
                if (rbase + t < n_mem) dst[rbase + t] = o[t];
        }
    }
#undef LDG_TILE
#undef STS_TILE
}

// ---------------- K3: per-query exact top-16 + gather + output packing -------
#define SEL_T 256

__global__ __launch_bounds__(SEL_T) void select_kernel(const float* __restrict__ mem,
                                                       float* __restrict__ out,
                                                       int n_mem) {
    const int q   = blockIdx.x;
    const int tid = threadIdx.x;
    const float* s = g_scores + (size_t)q * n_mem;

    // thread-local exact top-16 (strided coalesced scan)
    float ts[TOPK];
    int   ti[TOPK];
#pragma unroll
    for (int j = 0; j < TOPK; j++) { ts[j] = -FLT_MAX; ti[j] = 0x7FFFFFFF; }
    float tmin = -FLT_MAX;
    int   tminpos = 0;
    for (int r = tid; r < n_mem; r += SEL_T) {
        const float v = s[r];
        if (v > tmin) {
            ts[tminpos] = v; ti[tminpos] = r;
            tmin = ts[0]; tminpos = 0;
#pragma unroll
            for (int j = 1; j < TOPK; j++)
                if (ts[j] < tmin) { tmin = ts[j]; tminpos = j; }
        }
    }

    __shared__ float sv[SEL_T * TOPK];
    __shared__ int   si[SEL_T * TOPK];
    __shared__ float rv[SEL_T];
    __shared__ int   ri[SEL_T];
    __shared__ int   rp[SEL_T];
    __shared__ float wv[TOPK];
    __shared__ int   wi[TOPK];

#pragma unroll
    for (int j = 0; j < TOPK; j++) { sv[tid * TOPK + j] = ts[j]; si[tid * TOPK + j] = ti[j]; }
    __syncthreads();

    // 16 rounds of block argmax (ties -> smaller index, matching jax.lax.top_k)
    for (int kk = 0; kk < TOPK; kk++) {
        float best = -FLT_MAX; int besti = 0x7FFFFFFF; int bestp = 0;
        for (int j = tid; j < SEL_T * TOPK; j += SEL_T) {
            const float v = sv[j]; const int id = si[j];
            if (v > best || (v == best && id < besti)) { best = v; besti = id; bestp = j; }
        }
        rv[tid] = best; ri[tid] = besti; rp[tid] = bestp;
        __syncthreads();
        for (int st = SEL_T / 2; st > 0; st >>= 1) {
            if (tid < st) {
                if (rv[tid + st] > rv[tid] ||
                    (rv[tid + st] == rv[tid] && ri[tid + st] < ri[tid])) {
                    rv[tid] = rv[tid + st]; ri[tid] = ri[tid + st]; rp[tid] = rp[tid + st];
                }
            }
            __syncthreads();
        }
        if (tid == 0) { wv[kk] = rv[0]; wi[kk] = ri[0]; sv[rp[0]] = -FLT_MAX; }
        __syncthreads();
    }

    // outputs: [top_scores (NQ*16) | top_idx as float (NQ*16) | top_feats (NQ*16*256)]
    float* out_scores = out;
    float* out_idx    = out + NQ * TOPK;
    float* out_feats  = out + 2 * NQ * TOPK;

    if (tid < TOPK) {
        out_scores[q * TOPK + tid] = wv[tid];
        out_idx[q * TOPK + tid]    = (float)wi[tid];
    }
#pragma unroll 1
    for (int kk = 0; kk < TOPK; kk++) {
        const int id = wi[kk];
        out_feats[(size_t)(q * TOPK + kk) * OUT_DIM + tid] = mem[(size_t)id * OUT_DIM + tid];
    }
}

// ---------------- launch ------------------------------------------------------
extern "C" void kernel_launch(void* const* d_in, const int* in_sizes, int n_in,
                              void* d_out, int out_size) {
    const float* hidden = (const float*)d_in[0];
    const float* Wp     = (const float*)d_in[1];
    const float* bp     = (const float*)d_in[2];
    const float* mem    = (const float*)d_in[3];
    int n_mem = in_sizes[3] / OUT_DIM;
    if (n_mem > N_MEM_MAX) n_mem = N_MEM_MAX;

    qproj_kernel<<<NQ, OUT_DIM>>>(hidden, Wp, bp);
    const int nblk = (n_mem + TM - 1) / TM;
    score_kernel<<<nblk, 512>>>(mem, n_mem);
    select_kernel<<<NQ, SEL_T>>>(mem, (float*)d_out, n_mem);
}

// round 2
// speedup vs baseline: 2.3344x; 2.3344x over previous
#include <cuda_runtime.h>
#include <cuda_bf16.h>
#include <cfloat>
#include <cstdint>

#define NUM_HEADS 4
#define OUT_DIM   256
#define HID       512
#define NQ        256
#define TOPK      16
#define N_MEM_MAX 500000
#define CAND      32          // coarse candidates rescored exactly per query
#define NB3       240         // coarse-select blocks

// ---------------- static scratch ---------------------------------------------
__device__ __align__(16) float          g_q [NQ * OUT_DIM];    // fp32 queries (for exact rescore)
__device__ __align__(16) __nv_bfloat16  g_qb[NQ * OUT_DIM];    // bf16 queries (mma B operand)
__device__ __align__(16) __nv_bfloat16  g_coarse[(size_t)N_MEM_MAX * NQ]; // coarse scores [row][q]
__device__ float g_cand_val[NQ * NB3 * TOPK];
__device__ int   g_cand_idx[NQ * NB3 * TOPK];

// ---------------- K1: q = LN(hidden @ Wp + bp) -------------------------------
__global__ __launch_bounds__(256) void qproj_kernel(const float* __restrict__ hidden,
                                                    const float* __restrict__ Wp,
                                                    const float* __restrict__ bp) {
    __shared__ float hs[HID];
    __shared__ float ws[32][OUT_DIM];
    __shared__ float red[OUT_DIM];
    const int qidx = blockIdx.x;          // h*64 + b
    const int h = qidx >> 6;
    const int b = qidx & 63;
    const int d = threadIdx.x;

    for (int k = d; k < HID; k += OUT_DIM) hs[k] = hidden[b * HID + k];

    const int j = h * OUT_DIM + d;
    float acc = bp[j];
    for (int kc = 0; kc < HID; kc += 32) {
        __syncthreads();
#pragma unroll
        for (int i = 0; i < 32; i++) ws[i][d] = Wp[(kc + i) * (NUM_HEADS * OUT_DIM) + j];
        __syncthreads();
#pragma unroll
        for (int i = 0; i < 32; i++) acc += hs[kc + i] * ws[i][d];
    }

    red[d] = acc; __syncthreads();
    for (int s = 128; s > 0; s >>= 1) { if (d < s) red[d] += red[d + s]; __syncthreads(); }
    const float mean = red[0] * (1.0f / OUT_DIM);
    __syncthreads();
    const float dx = acc - mean;
    red[d] = dx * dx; __syncthreads();
    for (int s = 128; s > 0; s >>= 1) { if (d < s) red[d] += red[d + s]; __syncthreads(); }
    const float var = red[0] * (1.0f / OUT_DIM);

    const float o = dx * rsqrtf(var + 1e-5f);
    g_q [qidx * OUT_DIM + d] = o;
    g_qb[qidx * OUT_DIM + d] = __float2bfloat16(o);
}

// ---------------- K2: coarse scores via bf16 mma.sync ------------------------
#define K2_THREADS 512
#define RPB  512            // rows per block
#define SUBT 64             // rows per subtile
#define NSUB (RPB / SUBT)   // 8
#define LDB  264            // padded k-dim (bf16 elems): 528B rows, ldmatrix conflict-free
#define BS_BYTES (NQ * LDB * 2)       // 135168
#define AS_BYTES (SUBT * LDB * 2)     // 33792
#define K2_SMEM  (BS_BYTES + 2 * AS_BYTES)

__device__ __forceinline__ uint32_t smem_u32(const void* p) {
    return (uint32_t)__cvta_generic_to_shared(p);
}
__device__ __forceinline__ void ldsm_x4(uint32_t& r0, uint32_t& r1, uint32_t& r2, uint32_t& r3,
                                        uint32_t addr) {
    asm volatile("ldmatrix.sync.aligned.m8n8.x4.shared.b16 {%0,%1,%2,%3}, [%4];"
                 : "=r"(r0), "=r"(r1), "=r"(r2), "=r"(r3) : "r"(addr));
}
__device__ __forceinline__ void mma_bf16(float* d,
                                         uint32_t a0, uint32_t a1, uint32_t a2, uint32_t a3,
                                         uint32_t b0, uint32_t b1) {
    asm volatile("mma.sync.aligned.m16n8k16.row.col.f32.bf16.bf16.f32 "
                 "{%0,%1,%2,%3}, {%4,%5,%6,%7}, {%8,%9}, {%0,%1,%2,%3};"
                 : "+f"(d[0]), "+f"(d[1]), "+f"(d[2]), "+f"(d[3])
                 : "r"(a0), "r"(a1), "r"(a2), "r"(a3), "r"(b0), "r"(b1));
}

__global__ __launch_bounds__(K2_THREADS, 1) void score_kernel(const float* __restrict__ mem,
                                                              int n_mem) {
    extern __shared__ char smem[];
    __nv_bfloat16* Bs  = (__nv_bfloat16*)smem;                 // [256 q][LDB k]
    __nv_bfloat16* As0 = (__nv_bfloat16*)(smem + BS_BYTES);    // 2 x [64 row][LDB k]

    const int tid = threadIdx.x, lane = tid & 31, w = tid >> 5;
    const int rowbase = (w & 3) * 16;         // warp row offset within subtile
    const int qbase   = (w >> 2) * 64;        // warp query offset
    const int row0 = blockIdx.x * RPB;

    // load all 256 bf16 queries into smem (persistent)
    {
        const uint2* src = (const uint2*)g_qb;   // 4 bf16 per uint2
        for (int p = tid; p < NQ * 64; p += K2_THREADS) {
            const int r = p >> 6, c4 = p & 63;
            uint2 v = src[p];
            *(uint2*)(Bs + r * LDB + c4 * 4) = v;
        }
    }

    float4 pf[8];
#define LDG_SUB(s)                                                                   \
    do {                                                                             \
        _Pragma("unroll")                                                            \
        for (int i = 0; i < 8; i++) {                                                \
            const int p = tid + i * K2_THREADS;                                      \
            const int r = p >> 6, c4 = p & 63;                                       \
            const int rg = row0 + (s) * SUBT + r;                                    \
            pf[i] = (rg < n_mem)                                                     \
                ? __ldg((const float4*)(mem + (size_t)rg * OUT_DIM + c4 * 4))        \
                : make_float4(0.f, 0.f, 0.f, 0.f);                                   \
        }                                                                            \
    } while (0)

#define STS_SUB(bufi)                                                                \
    do {                                                                             \
        __nv_bfloat16* A = As0 + (bufi) * (SUBT * LDB);                              \
        _Pragma("unroll")                                                            \
        for (int i = 0; i < 8; i++) {                                                \
            const int p = tid + i * K2_THREADS;                                      \
            const int r = p >> 6, c4 = p & 63;                                       \
            __nv_bfloat162 lo = __float22bfloat162_rn(make_float2(pf[i].x, pf[i].y));\
            __nv_bfloat162 hi = __float22bfloat162_rn(make_float2(pf[i].z, pf[i].w));\
            uint2 u; u.x = *(uint32_t*)&lo; u.y = *(uint32_t*)&hi;                   \
            *(uint2*)(A + r * LDB + c4 * 4) = u;                                     \
        }                                                                            \
    } while (0)

    LDG_SUB(0);
    STS_SUB(0);
    __syncthreads();

    for (int s = 0; s < NSUB; s++) {
        if (s + 1 < NSUB) LDG_SUB(s + 1);
        const int buf = s & 1;
        const __nv_bfloat16* A = As0 + buf * (SUBT * LDB);
        const uint32_t aBase = smem_u32(A)  + (rowbase + (lane & 15)) * (LDB * 2) + (lane >> 4) * 16;
        const uint32_t bBase = smem_u32(Bs) + (qbase   + (lane & 15)) * (LDB * 2) + (lane >> 4) * 16;

        float acc[8][4];
#pragma unroll
        for (int nt = 0; nt < 8; nt++)
#pragma unroll
            for (int c = 0; c < 4; c++) acc[nt][c] = 0.f;

#pragma unroll
        for (int kt = 0; kt < 16; kt++) {
            uint32_t a0, a1, a2, a3;
            ldsm_x4(a0, a1, a2, a3, aBase + kt * 32);
#pragma unroll
            for (int nbp = 0; nbp < 4; nbp++) {
                uint32_t b0, b1, b2, b3;
                ldsm_x4(b0, b1, b2, b3, bBase + nbp * 16 * (LDB * 2) + kt * 32);
                mma_bf16(acc[nbp * 2 + 0], a0, a1, a2, a3, b0, b2);  // n-tile +0
                mma_bf16(acc[nbp * 2 + 1], a0, a1, a2, a3, b1, b3);  // n-tile +8
            }
        }

        // epilogue: coarse[row][q] bf16, coalesced bf162 stores
        const int rg0 = row0 + s * SUBT + rowbase + (lane >> 2);
#pragma unroll
        for (int nt = 0; nt < 8; nt++) {
            const int q = qbase + nt * 8 + (lane & 3) * 2;
            if (rg0 < n_mem)
                *(__nv_bfloat162*)(g_coarse + (size_t)rg0 * NQ + q) =
                    __float22bfloat162_rn(make_float2(acc[nt][0], acc[nt][1]));
            if (rg0 + 8 < n_mem)
                *(__nv_bfloat162*)(g_coarse + (size_t)(rg0 + 8) * NQ + q) =
                    __float22bfloat162_rn(make_float2(acc[nt][2], acc[nt][3]));
        }

        if (s + 1 < NSUB) STS_SUB(buf ^ 1);
        __syncthreads();
    }
#undef LDG_SUB
#undef STS_SUB
}

// ---------------- K3: per-block per-query coarse top-16 ----------------------
#define INS3(v, r)                                                       \
    do {                                                                 \
        ts[tminpos] = (v); ti[tminpos] = (r);                            \
        tmin = ts[0]; tminpos = 0;                                       \
        _Pragma("unroll")                                                \
        for (int jj = 1; jj < TOPK; jj++)                                \
            if (ts[jj] < tmin) { tmin = ts[jj]; tminpos = jj; }          \
    } while (0)

__global__ __launch_bounds__(256) void coarse_select_kernel(int n_mem) {
    const int q = threadIdx.x;     // one query per thread
    const int rows_per = (n_mem + NB3 - 1) / NB3;
    const int r0 = blockIdx.x * rows_per;
    const int r1 = min(r0 + rows_per, n_mem);

    float ts[TOPK]; int ti[TOPK];
#pragma unroll
    for (int j = 0; j < TOPK; j++) { ts[j] = -FLT_MAX; ti[j] = 0x7FFFFFFF; }
    float tmin = -FLT_MAX; int tminpos = 0;

    const __nv_bfloat16* base = g_coarse + q;
    int r = r0;
    for (; r + 4 <= r1; r += 4) {
        const float v0 = __bfloat162float(base[(size_t)(r + 0) * NQ]);
        const float v1 = __bfloat162float(base[(size_t)(r + 1) * NQ]);
        const float v2 = __bfloat162float(base[(size_t)(r + 2) * NQ]);
        const float v3 = __bfloat162float(base[(size_t)(r + 3) * NQ]);
        if (v0 > tmin) INS3(v0, r + 0);
        if (v1 > tmin) INS3(v1, r + 1);
        if (v2 > tmin) INS3(v2, r + 2);
        if (v3 > tmin) INS3(v3, r + 3);
    }
    for (; r < r1; r++) {
        const float v = __bfloat162float(base[(size_t)r * NQ]);
        if (v > tmin) INS3(v, r);
    }

    const int ob = (q * NB3 + blockIdx.x) * TOPK;
#pragma unroll
    for (int j = 0; j < TOPK; j++) { g_cand_val[ob + j] = ts[j]; g_cand_idx[ob + j] = ti[j]; }
}

// ---------------- K4: merge -> coarse top-32 -> exact rescore -> top-16 ------
#define P4 (NB3 * TOPK)   // 3840 candidates per query

__global__ __launch_bounds__(256) void final_kernel(const float* __restrict__ mem,
                                                    float* __restrict__ out, int n_mem) {
    const int q = blockIdx.x, tid = threadIdx.x, lane = tid & 31, w = tid >> 5;
    __shared__ float sv[P4];
    __shared__ int   si[P4];
    __shared__ float rv[256]; __shared__ int ri[256]; __shared__ int rp[256];
    __shared__ int   ci[CAND];
    __shared__ float ev[CAND];
    __shared__ float wv[TOPK]; __shared__ int wi[TOPK];

    for (int j = tid; j < P4; j += 256) { sv[j] = g_cand_val[q * P4 + j]; si[j] = g_cand_idx[q * P4 + j]; }
    __syncthreads();

    // coarse top-CAND (value desc, index asc on ties)
    for (int kk = 0; kk < CAND; kk++) {
        float best = -FLT_MAX; int besti = 0x7FFFFFFF, bestp = 0;
        for (int j = tid; j < P4; j += 256) {
            const float v = sv[j]; const int id = si[j];
            if (v > best || (v == best && id < besti)) { best = v; besti = id; bestp = j; }
        }
        rv[tid] = best; ri[tid] = besti; rp[tid] = bestp;
        __syncthreads();
        for (int st = 128; st > 0; st >>= 1) {
            if (tid < st) {
                if (rv[tid + st] > rv[tid] ||
                    (rv[tid + st] == rv[tid] && ri[tid + st] < ri[tid])) {
                    rv[tid] = rv[tid + st]; ri[tid] = ri[tid + st]; rp[tid] = rp[tid + st];
                }
            }
            __syncthreads();
        }
        if (tid == 0) { ci[kk] = ri[0]; sv[rp[0]] = -FLT_MAX; }
        __syncthreads();
    }

    // exact fp32 rescore of the 32 candidates
    const float* qv = g_q + q * OUT_DIM;
    for (int c = w; c < CAND; c += 8) {
        const float* row = mem + (size_t)ci[c] * OUT_DIM;
        float sum = 0.f;
#pragma unroll
        for (int d = lane; d < OUT_DIM; d += 32) sum += row[d] * qv[d];
#pragma unroll
        for (int o = 16; o; o >>= 1) sum += __shfl_xor_sync(0xffffffffu, sum, o);
        if (lane == 0) ev[c] = sum;
    }
    __syncthreads();

    // exact top-16 (value desc, index asc on ties) — serial over 32, trivial
    if (tid == 0) {
        bool used[CAND];
#pragma unroll
        for (int c = 0; c < CAND; c++) used[c] = false;
        for (int kk = 0; kk < TOPK; kk++) {
            float best = -FLT_MAX; int besti = 0x7FFFFFFF; int bp = 0;
            for (int c = 0; c < CAND; c++) {
                if (used[c]) continue;
                if (ev[c] > best || (ev[c] == best && ci[c] < besti)) {
                    best = ev[c]; besti = ci[c]; bp = c;
                }
            }
            used[bp] = true; wv[kk] = best; wi[kk] = besti;
        }
    }
    __syncthreads();

    float* out_scores = out;
    float* out_idx    = out + NQ * TOPK;
    float* out_feats  = out + 2 * NQ * TOPK;

    if (tid < TOPK) {
        out_scores[q * TOPK + tid] = wv[tid];
        out_idx[q * TOPK + tid]    = (float)wi[tid];
    }
#pragma unroll 1
    for (int kk = 0; kk < TOPK; kk++)
        out_feats[(size_t)(q * TOPK + kk) * OUT_DIM + tid] = mem[(size_t)wi[kk] * OUT_DIM + tid];
}

// ---------------- launch ------------------------------------------------------
extern "C" void kernel_launch(void* const* d_in, const int* in_sizes, int n_in,
                              void* d_out, int out_size) {
    const float* hidden = (const float*)d_in[0];
    const float* Wp     = (const float*)d_in[1];
    const float* bp     = (const float*)d_in[2];
    const float* mem    = (const float*)d_in[3];
    int n_mem = in_sizes[3] / OUT_DIM;
    if (n_mem > N_MEM_MAX) n_mem = N_MEM_MAX;

    cudaFuncSetAttribute(score_kernel, cudaFuncAttributeMaxDynamicSharedMemorySize, K2_SMEM);

    qproj_kernel<<<NQ, 256>>>(hidden, Wp, bp);
    const int nblk = (n_mem + RPB - 1) / RPB;
    score_kernel<<<nblk, K2_THREADS, K2_SMEM>>>(mem, n_mem);
    coarse_select_kernel<<<NB3, 256>>>(n_mem);
    final_kernel<<<NQ, 256>>>(mem, (float*)d_out, n_mem);
}

// round 3
// speedup vs baseline: 3.6308x; 1.5554x over previous
#include <cuda_runtime.h>
#include <cuda_bf16.h>
#include <cfloat>
#include <cstdint>

#define NUM_HEADS 4
#define OUT_DIM   256
#define HID       512
#define NQ        256
#define TOPK      16
#define N_MEM_MAX 500000
#define CAND      32

#define RPB     512
#define NB_K2   ((N_MEM_MAX + RPB - 1) / RPB)   // 977
#define CPB     4                               // candidates / block / query
#define POOL_MAX (NB_K2 * CPB)                  // 3908

// ---------------- static scratch ---------------------------------------------
__device__ __align__(16) float          g_qpre[64 * NUM_HEADS * OUT_DIM];
__device__ __align__(16) float          g_q [NQ * OUT_DIM];
__device__ __align__(16) __nv_bfloat16  g_qb[NQ * OUT_DIM];
__device__ float g_cand_val[NQ * POOL_MAX];
__device__ int   g_cand_idx[NQ * POOL_MAX];

// ---------------- K1a: proj = hidden @ Wp + bp (Wp read exactly once) --------
__global__ __launch_bounds__(256) void proj_kernel(const float* __restrict__ hidden,
                                                   const float* __restrict__ Wp,
                                                   const float* __restrict__ bp) {
    const int tid = threadIdx.x;
    const int j   = blockIdx.x * 32 + (tid & 31);      // output column
    const int b0  = (tid >> 5) * 8;                    // 8 batch rows per thread
    float acc[8];
#pragma unroll
    for (int i = 0; i < 8; i++) acc[i] = 0.f;
#pragma unroll 4
    for (int k = 0; k < HID; k++) {
        const float wv = __ldg(&Wp[k * (NUM_HEADS * OUT_DIM) + j]);
#pragma unroll
        for (int i = 0; i < 8; i++)
            acc[i] = fmaf(__ldg(&hidden[(b0 + i) * HID + k]), wv, acc[i]);
    }
    const float bias = __ldg(&bp[j]);
#pragma unroll
    for (int i = 0; i < 8; i++)
        g_qpre[(b0 + i) * (NUM_HEADS * OUT_DIM) + j] = acc[i] + bias;
}

// ---------------- K1b: layernorm per (head, batch) row -----------------------
__global__ __launch_bounds__(256) void ln_kernel() {
    __shared__ float red[OUT_DIM];
    const int qidx = blockIdx.x;          // h*64 + b
    const int h = qidx >> 6, b = qidx & 63, d = threadIdx.x;

    const float x = g_qpre[b * (NUM_HEADS * OUT_DIM) + h * OUT_DIM + d];
    red[d] = x; __syncthreads();
    for (int s = 128; s > 0; s >>= 1) { if (d < s) red[d] += red[d + s]; __syncthreads(); }
    const float mean = red[0] * (1.0f / OUT_DIM);
    __syncthreads();
    const float dx = x - mean;
    red[d] = dx * dx; __syncthreads();
    for (int s = 128; s > 0; s >>= 1) { if (d < s) red[d] += red[d + s]; __syncthreads(); }
    const float var = red[0] * (1.0f / OUT_DIM);

    const float o = dx * rsqrtf(var + 1e-5f);
    g_q [qidx * OUT_DIM + d] = o;
    g_qb[qidx * OUT_DIM + d] = __float2bfloat16(o);
}

// ---------------- K2: bf16 mma scores + fused per-block top-4 ----------------
#define K2_THREADS 256
#define SUBT 32
#define NSUB (RPB / SUBT)              // 16
#define LDB  264                       // padded k (bf16): 528B rows, ldsm conflict-free
#define SBP  258                       // score buffer row stride (bf16)
#define BS_BYTES (NQ * LDB * 2)        // 135168
#define AS_BYTES (SUBT * LDB * 2)      // 16896
#define SB_BYTES (SUBT * SBP * 2)      // 16512
#define K2_SMEM  (BS_BYTES + 2 * AS_BYTES + SB_BYTES)   // 185472

__device__ __forceinline__ uint32_t smem_u32(const void* p) {
    return (uint32_t)__cvta_generic_to_shared(p);
}
__device__ __forceinline__ void ldsm_x4(uint32_t& r0, uint32_t& r1, uint32_t& r2, uint32_t& r3,
                                        uint32_t addr) {
    asm volatile("ldmatrix.sync.aligned.m8n8.x4.shared.b16 {%0,%1,%2,%3}, [%4];"
                 : "=r"(r0), "=r"(r1), "=r"(r2), "=r"(r3) : "r"(addr));
}
__device__ __forceinline__ void mma_bf16(float* d,
                                         uint32_t a0, uint32_t a1, uint32_t a2, uint32_t a3,
                                         uint32_t b0, uint32_t b1) {
    asm volatile("mma.sync.aligned.m16n8k16.row.col.f32.bf16.bf16.f32 "
                 "{%0,%1,%2,%3}, {%4,%5,%6,%7}, {%8,%9}, {%0,%1,%2,%3};"
                 : "+f"(d[0]), "+f"(d[1]), "+f"(d[2]), "+f"(d[3])
                 : "r"(a0), "r"(a1), "r"(a2), "r"(a3), "r"(b0), "r"(b1));
}

#define INS4(v, r)                                                        \
    do {                                                                  \
        t4v[tminpos] = (v); t4i[tminpos] = (r);                           \
        tmin = t4v[0]; tminpos = 0;                                       \
        _Pragma("unroll")                                                 \
        for (int jj = 1; jj < CPB; jj++)                                  \
            if (t4v[jj] < tmin) { tmin = t4v[jj]; tminpos = jj; }         \
    } while (0)

__global__ __launch_bounds__(K2_THREADS, 1) void score_kernel(const float* __restrict__ mem,
                                                              int n_mem) {
    extern __shared__ char smem[];
    __nv_bfloat16* Bs  = (__nv_bfloat16*)smem;                               // [256 q][LDB]
    __nv_bfloat16* As0 = (__nv_bfloat16*)(smem + BS_BYTES);                  // 2 x [32 r][LDB]
    __nv_bfloat16* Sb  = (__nv_bfloat16*)(smem + BS_BYTES + 2 * AS_BYTES);   // [32 r][SBP]

    const int tid = threadIdx.x, lane = tid & 31, w = tid >> 5;
    const int qgroup = w * 32;
    const int row0 = blockIdx.x * RPB;

    // persistent B (all 256 bf16 queries)
    {
        const uint2* src = (const uint2*)g_qb;
        for (int p = tid; p < NQ * 64; p += K2_THREADS) {
            const int r = p >> 6, c4 = p & 63;
            *(uint2*)(Bs + r * LDB + c4 * 4) = src[p];
        }
    }

    // per-query (thread = query) block-local top-4
    float t4v[CPB]; int t4i[CPB];
#pragma unroll
    for (int j = 0; j < CPB; j++) { t4v[j] = -FLT_MAX; t4i[j] = 0x7FFFFFFF; }
    float tmin = -FLT_MAX; int tminpos = 0;

    float4 pf[8];
#define LDG_SUB(s)                                                                   \
    do {                                                                             \
        _Pragma("unroll")                                                            \
        for (int i = 0; i < 8; i++) {                                                \
            const int p = tid + i * K2_THREADS;                                      \
            const int r = p >> 6, c4 = p & 63;                                       \
            const int rg = row0 + (s) * SUBT + r;                                    \
            pf[i] = (rg < n_mem)                                                     \
                ? __ldg((const float4*)(mem + (size_t)rg * OUT_DIM + c4 * 4))        \
                : make_float4(0.f, 0.f, 0.f, 0.f);                                   \
        }                                                                            \
    } while (0)

#define STS_SUB(bufi)                                                                \
    do {                                                                             \
        __nv_bfloat16* A = As0 + (bufi) * (SUBT * LDB);                              \
        _Pragma("unroll")                                                            \
        for (int i = 0; i < 8; i++) {                                                \
            const int p = tid + i * K2_THREADS;                                      \
            const int r = p >> 6, c4 = p & 63;                                       \
            __nv_bfloat162 lo = __float22bfloat162_rn(make_float2(pf[i].x, pf[i].y));\
            __nv_bfloat162 hi = __float22bfloat162_rn(make_float2(pf[i].z, pf[i].w));\
            uint2 u; u.x = *(uint32_t*)&lo; u.y = *(uint32_t*)&hi;                   \
            *(uint2*)(A + r * LDB + c4 * 4) = u;                                     \
        }                                                                            \
    } while (0)

    LDG_SUB(0);
    STS_SUB(0);
    __syncthreads();

    const uint32_t bBase = smem_u32(Bs) + (qgroup + (lane & 15)) * (LDB * 2) + (lane >> 4) * 16;

    int cur = 0;
    for (int s = 0; s < NSUB; s++) {
        if (s + 1 < NSUB) LDG_SUB(s + 1);
        const uint32_t aBase = smem_u32(As0 + cur * (SUBT * LDB))
                             + (lane & 15) * (LDB * 2) + (lane >> 4) * 16;

        float acc[2][4][4];
#pragma unroll
        for (int mt = 0; mt < 2; mt++)
#pragma unroll
            for (int nt = 0; nt < 4; nt++)
#pragma unroll
                for (int c = 0; c < 4; c++) acc[mt][nt][c] = 0.f;

#pragma unroll
        for (int kt = 0; kt < 16; kt++) {
            uint32_t a[2][4];
            ldsm_x4(a[0][0], a[0][1], a[0][2], a[0][3], aBase + kt * 32);
            ldsm_x4(a[1][0], a[1][1], a[1][2], a[1][3], aBase + 16 * (LDB * 2) + kt * 32);
#pragma unroll
            for (int nbp = 0; nbp < 2; nbp++) {
                uint32_t b0, b1, b2, b3;
                ldsm_x4(b0, b1, b2, b3, bBase + nbp * 16 * (LDB * 2) + kt * 32);
#pragma unroll
                for (int mt = 0; mt < 2; mt++) {
                    mma_bf16(acc[mt][nbp * 2 + 0], a[mt][0], a[mt][1], a[mt][2], a[mt][3], b0, b2);
                    mma_bf16(acc[mt][nbp * 2 + 1], a[mt][0], a[mt][1], a[mt][2], a[mt][3], b1, b3);
                }
            }
        }

        if (s + 1 < NSUB) STS_SUB(cur ^ 1);

        // scores -> smem tile [32 rows][256 q]
#pragma unroll
        for (int mt = 0; mt < 2; mt++) {
            const int rl = mt * 16 + (lane >> 2);
#pragma unroll
            for (int nt = 0; nt < 4; nt++) {
                const int q = qgroup + nt * 8 + (lane & 3) * 2;
                *(__nv_bfloat162*)(Sb + rl * SBP + q) =
                    __float22bfloat162_rn(make_float2(acc[mt][nt][0], acc[mt][nt][1]));
                *(__nv_bfloat162*)(Sb + (rl + 8) * SBP + q) =
                    __float22bfloat162_rn(make_float2(acc[mt][nt][2], acc[mt][nt][3]));
            }
        }
        __syncthreads();

        // fused selection: thread tid owns query tid
        const int rb = row0 + s * SUBT;
#pragma unroll 4
        for (int r = 0; r < SUBT; r++) {
            const float v = __bfloat162float(Sb[r * SBP + tid]);
            if (v > tmin && rb + r < n_mem) INS4(v, rb + r);
        }
        __syncthreads();
        cur ^= 1;
    }

    const int ob = (tid * NB_K2 + blockIdx.x) * CPB;
#pragma unroll
    for (int j = 0; j < CPB; j++) { g_cand_val[ob + j] = t4v[j]; g_cand_idx[ob + j] = t4i[j]; }
#undef LDG_SUB
#undef STS_SUB
}

// ---------------- K3: merge -> coarse top-32 -> exact rescore -> top-16 ------
__global__ __launch_bounds__(256) void final_kernel(const float* __restrict__ mem,
                                                    float* __restrict__ out,
                                                    int n_mem, int nblk) {
    __shared__ float sv[POOL_MAX];
    __shared__ int   si[POOL_MAX];
    __shared__ float swv[8]; __shared__ int swi[8]; __shared__ int swp[8];
    __shared__ int   ci[CAND];
    __shared__ float ev[CAND];
    __shared__ float wv[TOPK]; __shared__ int wi[TOPK];

    const int q = blockIdx.x, tid = threadIdx.x, lane = tid & 31, w = tid >> 5;
    const int P = nblk * CPB;

    for (int j = tid; j < P; j += 256) {
        sv[j] = g_cand_val[q * POOL_MAX + j];
        si[j] = g_cand_idx[q * POOL_MAX + j];
    }
    __syncthreads();

    // 32 rounds of block argmax (value desc, index asc) — shuffle-based, 2 syncs
    for (int kk = 0; kk < CAND; kk++) {
        float best = -FLT_MAX; int besti = 0x7FFFFFFF, bestp = 0;
        for (int j = tid; j < P; j += 256) {
            const float v = sv[j]; const int id = si[j];
            if (v > best || (v == best && id < besti)) { best = v; besti = id; bestp = j; }
        }
#pragma unroll
        for (int o = 16; o; o >>= 1) {
            const float ov = __shfl_down_sync(0xffffffffu, best, o);
            const int   oi = __shfl_down_sync(0xffffffffu, besti, o);
            const int   op = __shfl_down_sync(0xffffffffu, bestp, o);
            if (ov > best || (ov == best && oi < besti)) { best = ov; besti = oi; bestp = op; }
        }
        if (lane == 0) { swv[w] = best; swi[w] = besti; swp[w] = bestp; }
        __syncthreads();
        if (tid < 8) {
            best = swv[tid]; besti = swi[tid]; bestp = swp[tid];
#pragma unroll
            for (int o = 4; o; o >>= 1) {
                const float ov = __shfl_down_sync(0xffu, best, o);
                const int   oi = __shfl_down_sync(0xffu, besti, o);
                const int   op = __shfl_down_sync(0xffu, bestp, o);
                if (ov > best || (ov == best && oi < besti)) { best = ov; besti = oi; bestp = op; }
            }
            if (tid == 0) { ci[kk] = besti; sv[bestp] = -FLT_MAX; }
        }
        __syncthreads();
    }

    // exact fp32 rescore
    const float* qv = g_q + q * OUT_DIM;
    for (int c = w; c < CAND; c += 8) {
        const int id = ci[c];
        float sum = 0.f;
        if (id < n_mem) {
            const float* row = mem + (size_t)id * OUT_DIM;
#pragma unroll
            for (int d = lane; d < OUT_DIM; d += 32) sum += row[d] * qv[d];
        }
#pragma unroll
        for (int o = 16; o; o >>= 1) sum += __shfl_xor_sync(0xffffffffu, sum, o);
        if (lane == 0) ev[c] = (id < n_mem) ? sum : -FLT_MAX;
    }
    __syncthreads();

    // exact top-16 of 32 (value desc, index asc)
    if (tid == 0) {
        unsigned used = 0;
        for (int kk = 0; kk < TOPK; kk++) {
            float best = -FLT_MAX; int besti = 0x7FFFFFFF; int bp = 0;
            for (int c = 0; c < CAND; c++) {
                if (used & (1u << c)) continue;
                if (ev[c] > best || (ev[c] == best && ci[c] < besti)) {
                    best = ev[c]; besti = ci[c]; bp = c;
                }
            }
            used |= (1u << bp); wv[kk] = best; wi[kk] = besti;
        }
    }
    __syncthreads();

    float* out_scores = out;
    float* out_idx    = out + NQ * TOPK;
    float* out_feats  = out + 2 * NQ * TOPK;

    if (tid < TOPK) {
        out_scores[q * TOPK + tid] = wv[tid];
        out_idx[q * TOPK + tid]    = (float)wi[tid];
    }
#pragma unroll 1
    for (int kk = 0; kk < TOPK; kk++)
        out_feats[(size_t)(q * TOPK + kk) * OUT_DIM + tid] = mem[(size_t)wi[kk] * OUT_DIM + tid];
}

// ---------------- launch ------------------------------------------------------
extern "C" void kernel_launch(void* const* d_in, const int* in_sizes, int n_in,
                              void* d_out, int out_size) {
    const float* hidden = (const float*)d_in[0];
    const float* Wp     = (const float*)d_in[1];
    const float* bp     = (const float*)d_in[2];
    const float* mem    = (const float*)d_in[3];
    int n_mem = in_sizes[3] / OUT_DIM;
    if (n_mem > N_MEM_MAX) n_mem = N_MEM_MAX;
    const int nblk = (n_mem + RPB - 1) / RPB;

    cudaFuncSetAttribute(score_kernel, cudaFuncAttributeMaxDynamicSharedMemorySize, K2_SMEM);

    proj_kernel<<<(NUM_HEADS * OUT_DIM) / 32, 256>>>(hidden, Wp, bp);
    ln_kernel<<<NQ, 256>>>();
    score_kernel<<<nblk, K2_THREADS, K2_SMEM>>>(mem, n_mem);
    final_kernel<<<NQ, 256>>>(mem, (float*)d_out, n_mem, nblk);
}